// round 13
// baseline (speedup 1.0000x reference)
#include <cuda_runtime.h>
#include <cuda_bf16.h>
#include <math.h>
#include <stdint.h>

// Problem constants
#define TOK   100352          // 2*16*56*56
#define C     384
#define C3    1152
#define HID   1536
#define NHEAD 12
#define HD    32
#define NWIN  1568            // 2 * 4*14*14

// ---------------------------------------------------------------------------
// Scratch (device globals; allocation-free)
// ---------------------------------------------------------------------------
__device__ __nv_bfloat16 s_hb   [(size_t)TOK * C];
__device__ __nv_bfloat16 s_qkvb [(size_t)TOK * C3];
__device__ __nv_bfloat16 s_attnb[(size_t)TOK * C];
__device__ float         s_x2   [(size_t)TOK * C];
__device__ __nv_bfloat16 s_gb   [(size_t)TOK * HID];
__device__ float         s_bm   [8 * NHEAD * 64 * 64];
// bf16 weight copies ([K][N] row-major)
__device__ __nv_bfloat16 s_wqkv [(size_t)C * C3];
__device__ __nv_bfloat16 s_wproj[(size_t)C * C];
__device__ __nv_bfloat16 s_wfc1 [(size_t)C * HID];
__device__ __nv_bfloat16 s_wfc2 [(size_t)HID * C];

// ---------------------------------------------------------------------------
// fp32 -> bf16 conversion (weights, once per launch)
// ---------------------------------------------------------------------------
__global__ void f2bf_kernel(const float* __restrict__ in,
                            __nv_bfloat16* __restrict__ out, int n)
{
    int i = blockIdx.x * 256 + threadIdx.x;
    if (i < n) out[i] = __float2bfloat16(in[i]);
}

// ---------------------------------------------------------------------------
// Bias+mask table: [wtype 0..7][head][i][j]
// ---------------------------------------------------------------------------
__global__ void biasmask_kernel(const float* __restrict__ rpb,
                                float* __restrict__ bm)
{
    int wtype = blockIdx.x, head = blockIdx.y;
    int bd = (wtype >> 2) & 1, bh = (wtype >> 1) & 1, bw = wtype & 1;
    float* dst = bm + ((size_t)(wtype * NHEAD + head)) * 4096;
    for (int e = threadIdx.x; e < 4096; e += 256) {
        int i = e >> 6, j = e & 63;
        int odi = i >> 4, ohi = (i >> 2) & 3, owi = i & 3;
        int odj = j >> 4, ohj = (j >> 2) & 3, owj = j & 3;
        int li = (bd ? 1 + (odi >> 1) : 0) * 9 + (bh ? 1 + (ohi >> 1) : 0) * 3
               + (bw ? 1 + (owi >> 1) : 0);
        int lj = (bd ? 1 + (odj >> 1) : 0) * 9 + (bh ? 1 + (ohj >> 1) : 0) * 3
               + (bw ? 1 + (owj >> 1) : 0);
        float v = rpb[((odi - odj + 3) * 49 + (ohi - ohj + 3) * 7 +
                       (owi - owj + 3)) * NHEAD + head];
        if (li != lj) v -= 100.0f;
        dst[e] = v;
    }
}

// ---------------------------------------------------------------------------
// LayerNorm: one warp per token, C=384, bf16 output
// ---------------------------------------------------------------------------
__global__ void ln_kernel(const float* __restrict__ x,
                          const float* __restrict__ g,
                          const float* __restrict__ b,
                          __nv_bfloat16* __restrict__ y)
{
    int token = blockIdx.x * 8 + (threadIdx.x >> 5);
    int lane  = threadIdx.x & 31;
    const float* xr = x + (size_t)token * C;
    float v[12];
    float s = 0.f;
#pragma unroll
    for (int i = 0; i < 12; i++) { v[i] = xr[lane + i * 32]; s += v[i]; }
#pragma unroll
    for (int o = 16; o; o >>= 1) s += __shfl_xor_sync(0xffffffffu, s, o);
    float mu = s * (1.0f / 384.0f);
    float q = 0.f;
#pragma unroll
    for (int i = 0; i < 12; i++) { float d = v[i] - mu; q += d * d; }
#pragma unroll
    for (int o = 16; o; o >>= 1) q += __shfl_xor_sync(0xffffffffu, q, o);
    float rstd = rsqrtf(q * (1.0f / 384.0f) + 1e-5f);
    __nv_bfloat16* yr = y + (size_t)token * C;
#pragma unroll
    for (int i = 0; i < 12; i++) {
        int c = lane + i * 32;
        yr[c] = __float2bfloat16((v[i] - mu) * rstd * g[c] + b[c]);
    }
}

// ---------------------------------------------------------------------------
// MMA helpers
// ---------------------------------------------------------------------------
__device__ __forceinline__ float gelu_exact(float x)
{
    return 0.5f * x * (1.0f + erff(x * 0.70710678118654752f));
}

__device__ __forceinline__ void cp_async16(void* smem, const void* gmem)
{
    uint32_t s = (uint32_t)__cvta_generic_to_shared(smem);
    asm volatile("cp.async.cg.shared.global [%0], [%1], 16;\n" :: "r"(s), "l"(gmem));
}
__device__ __forceinline__ void cp_commit()
{
    asm volatile("cp.async.commit_group;\n");
}
template <int N>
__device__ __forceinline__ void cp_wait()
{
    asm volatile("cp.async.wait_group %0;\n" :: "n"(N));
}

__device__ __forceinline__ void ldsm_x4(uint32_t* r, const void* p)
{
    uint32_t a = (uint32_t)__cvta_generic_to_shared(p);
    asm volatile("ldmatrix.sync.aligned.m8n8.x4.shared.b16 {%0,%1,%2,%3}, [%4];"
                 : "=r"(r[0]), "=r"(r[1]), "=r"(r[2]), "=r"(r[3]) : "r"(a));
}
__device__ __forceinline__ void ldsm_x4_t(uint32_t* r, const void* p)
{
    uint32_t a = (uint32_t)__cvta_generic_to_shared(p);
    asm volatile("ldmatrix.sync.aligned.m8n8.x4.trans.shared.b16 {%0,%1,%2,%3}, [%4];"
                 : "=r"(r[0]), "=r"(r[1]), "=r"(r[2]), "=r"(r[3]) : "r"(a));
}

__device__ __forceinline__ void mma_bf16(float* d, const uint32_t* a,
                                         uint32_t b0, uint32_t b1)
{
    asm volatile(
        "mma.sync.aligned.m16n8k16.row.col.f32.bf16.bf16.f32 "
        "{%0,%1,%2,%3}, {%4,%5,%6,%7}, {%8,%9}, {%0,%1,%2,%3};\n"
        : "+f"(d[0]), "+f"(d[1]), "+f"(d[2]), "+f"(d[3])
        : "r"(a[0]), "r"(a[1]), "r"(a[2]), "r"(a[3]), "r"(b0), "r"(b1));
}

__device__ __forceinline__ uint32_t packbf(float a, float b)
{
    __nv_bfloat162 t = __floats2bfloat162_rn(a, b);
    return *(uint32_t*)&t;
}

// ---------------------------------------------------------------------------
// bf16 tensor-core GEMM: 256x128 CTA tile, BK=64, 3-stage cp.async ring,
// one __syncthreads per K-chunk. 256 threads = 8 warps (4M x 2N),
// warp tile 64x64 -> 32 mma per 8 ldmatrix per k16 step.
// A bf16 [M][K], B bf16 [K][N]. fp32 accumulate.
// ---------------------------------------------------------------------------
#define GSTAGES 3
#define A_STG   (256 * 72)        // bf16 elems per A stage (72 = 64 + 8 pad)
#define B_STG   (64 * 136)        // bf16 elems per B stage (136 = 128 + 8 pad)
#define GT_SMEM ((GSTAGES * (A_STG + B_STG)) * 2)   // 160.5 KB

// OUTBF: 0 -> write fp32 Cout; 1 -> write bf16 Coutb
template <int ACT, int RES, int OUTBF>
__global__ __launch_bounds__(256, 1)
void gemm_bf16_kernel(const __nv_bfloat16* __restrict__ A,
                      const __nv_bfloat16* __restrict__ B,
                      const float* __restrict__ bias,
                      const float* __restrict__ res,
                      float* __restrict__ Cout,
                      __nv_bfloat16* __restrict__ Coutb,
                      int M, int N, int K)
{
    extern __shared__ __nv_bfloat16 sm[];
    __nv_bfloat16* As = sm;                     // [GSTAGES][256][72]
    __nv_bfloat16* Bs = sm + GSTAGES * A_STG;   // [GSTAGES][64][136]

    int tid  = threadIdx.x;
    int lane = tid & 31;
    int wid  = tid >> 5;
    int wm   = wid & 3;        // warp row 0..3 (64 rows each)
    int wn   = wid >> 2;       // warp col 0..1 (64 cols each)
    int bm   = blockIdx.y * 256;
    int bn   = blockIdx.x * 128;

    float acc[4][8][4];
#pragma unroll
    for (int i = 0; i < 4; i++)
#pragma unroll
        for (int j = 0; j < 8; j++)
#pragma unroll
            for (int l = 0; l < 4; l++) acc[i][j][l] = 0.f;

    const int CH = K >> 6;      // 64-wide K chunks

    auto fill = [&](int c) {
        int s = c % GSTAGES;
        __nv_bfloat16* aS = As + s * A_STG;
        __nv_bfloat16* bS = Bs + s * B_STG;
        const __nv_bfloat16* ag = A + (size_t)bm * K + c * 64;
        const __nv_bfloat16* bg = B + (size_t)(c * 64) * N + bn;
#pragma unroll
        for (int i = 0; i < 8; i++) {           // A: 256 rows x 8 chunks of 8
            int idx = tid + i * 256;
            int row = idx >> 3, c8 = idx & 7;
            cp_async16(aS + row * 72 + c8 * 8,
                       ag + (size_t)row * K + c8 * 8);
        }
#pragma unroll
        for (int i = 0; i < 4; i++) {           // B: 64 rows x 16 chunks of 8
            int idx = tid + i * 256;
            int row = idx >> 4, c16 = idx & 15;
            cp_async16(bS + row * 136 + c16 * 8,
                       bg + (size_t)row * N + c16 * 8);
        }
        cp_commit();
    };

    fill(0);
    fill(1);

    for (int kt = 0; kt < CH; kt++) {
        cp_wait<1>();
        __syncthreads();
        if (kt + 2 < CH) fill(kt + 2); else cp_commit();

        int cur = kt % GSTAGES;
        const __nv_bfloat16* aS = As + cur * A_STG;
        const __nv_bfloat16* bS = Bs + cur * B_STG;

#pragma unroll
        for (int ks = 0; ks < 4; ks++) {
            uint32_t af[4][4];
            uint32_t bf[4][4];
#pragma unroll
            for (int mt = 0; mt < 4; mt++)
                ldsm_x4(af[mt], aS + (wm * 64 + mt * 16 + (lane & 15)) * 72
                                   + ks * 16 + (lane >> 4) * 8);
#pragma unroll
            for (int np = 0; np < 4; np++)
                ldsm_x4_t(bf[np], bS + (ks * 16 + (lane & 15)) * 136
                                     + wn * 64 + np * 16 + (lane >> 4) * 8);
#pragma unroll
            for (int mt = 0; mt < 4; mt++)
#pragma unroll
                for (int np = 0; np < 4; np++) {
                    mma_bf16(acc[mt][np * 2],     af[mt], bf[np][0], bf[np][1]);
                    mma_bf16(acc[mt][np * 2 + 1], af[mt], bf[np][2], bf[np][3]);
                }
        }
    }

    // epilogue
#pragma unroll
    for (int mt = 0; mt < 4; mt++) {
        int row = bm + wm * 64 + mt * 16 + (lane >> 2);
#pragma unroll
        for (int nt = 0; nt < 8; nt++) {
            int col = bn + wn * 64 + nt * 8 + (lane & 3) * 2;
            float bv0 = bias[col], bv1 = bias[col + 1];

            float v0 = acc[mt][nt][0] + bv0;
            float v1 = acc[mt][nt][1] + bv1;
            float v2 = acc[mt][nt][2] + bv0;
            float v3 = acc[mt][nt][3] + bv1;
            if (ACT) {
                v0 = gelu_exact(v0); v1 = gelu_exact(v1);
                v2 = gelu_exact(v2); v3 = gelu_exact(v3);
            }
            if (RES) {
                float2 q0 = *(const float2*)(res + (size_t)row * N + col);
                float2 q1 = *(const float2*)(res + (size_t)(row + 8) * N + col);
                v0 += q0.x; v1 += q0.y; v2 += q1.x; v3 += q1.y;
            }
            if (OUTBF) {
                *(uint32_t*)(Coutb + (size_t)row * N + col)       = packbf(v0, v1);
                *(uint32_t*)(Coutb + (size_t)(row + 8) * N + col) = packbf(v2, v3);
            } else {
                *(float2*)(Cout + (size_t)row * N + col)       = make_float2(v0, v1);
                *(float2*)(Cout + (size_t)(row + 8) * N + col) = make_float2(v2, v3);
            }
        }
    }
}

// ---------------------------------------------------------------------------
// Tensor-core attention: one block per (window, head), 128 threads (4 warps).
// ---------------------------------------------------------------------------
__global__ __launch_bounds__(128)
void attn_mma_kernel(const __nv_bfloat16* __restrict__ qkv,
                     const float* __restrict__ bm,
                     __nv_bfloat16* __restrict__ out)
{
    __shared__ __nv_bfloat16 Qs[64][40];
    __shared__ __nv_bfloat16 Ks[64][40];
    __shared__ __nv_bfloat16 Vs[64][40];
    __shared__ int sidx[64];

    int wi = blockIdx.x, head = blockIdx.y;
    int tid = threadIdx.x;
    int lane = tid & 31, w = tid >> 5;

    int b  = wi / 784;
    int rem = wi % 784;
    int wd = rem / 196;
    int r2 = rem % 196;
    int wh = r2 / 14;
    int ww = r2 % 14;
    int wtype = ((wd == 3) ? 4 : 0) | ((wh == 13) ? 2 : 0) | ((ww == 13) ? 1 : 0);

    if (tid < 64) {
        int od = tid >> 4, oh = (tid >> 2) & 3, ow = tid & 3;
        int d = wd * 4 + od, h = wh * 4 + oh, wq = ww * 4 + ow;
        int sd = (d + 2) & 15;
        int sh = h + 2; if (sh >= 56) sh -= 56;
        int sw = wq + 2; if (sw >= 56) sw -= 56;
        sidx[tid] = ((b * 16 + sd) * 56 + sh) * 56 + sw;
    }
    __syncthreads();

    for (int e = tid; e < 768; e += 128) {
        int tens = e >> 8;
        int r = e & 255;
        int n = r >> 2, c = r & 3;
        const uint4* src = (const uint4*)(qkv + (size_t)sidx[n] * C3 +
                                          tens * C + head * HD) + c;
        uint4 v = *src;
        __nv_bfloat16* dst = (tens == 0) ? &Qs[n][c * 8]
                           : (tens == 1) ? &Ks[n][c * 8] : &Vs[n][c * 8];
        *(uint4*)dst = v;
    }
    __syncthreads();

    float accs[8][4];
#pragma unroll
    for (int i = 0; i < 8; i++)
#pragma unroll
        for (int j = 0; j < 4; j++) accs[i][j] = 0.f;

#pragma unroll
    for (int ks = 0; ks < 2; ks++) {
        uint32_t qa[4];
        ldsm_x4(qa, &Qs[w * 16 + (lane & 15)][ks * 16 + (lane >> 4) * 8]);
#pragma unroll
        for (int nt = 0; nt < 4; nt++) {
            uint32_t kb[4];
            ldsm_x4(kb, &Ks[nt * 16 + ((lane >> 4) & 1) * 8 + (lane & 7)]
                        [ks * 16 + ((lane >> 3) & 1) * 8]);
            mma_bf16(accs[nt * 2],     qa, kb[0], kb[1]);
            mma_bf16(accs[nt * 2 + 1], qa, kb[2], kb[3]);
        }
    }

    const float scale = 0.17677669529663687f;
    int ri = w * 16 + (lane >> 2);
    const float* bmp = bm + ((size_t)(wtype * NHEAD + head)) * 4096;
#pragma unroll
    for (int nt = 0; nt < 8; nt++) {
        int j = nt * 8 + (lane & 3) * 2;
        float2 b0 = *(const float2*)(bmp + ri * 64 + j);
        float2 b1 = *(const float2*)(bmp + (ri + 8) * 64 + j);
        accs[nt][0] = accs[nt][0] * scale + b0.x;
        accs[nt][1] = accs[nt][1] * scale + b0.y;
        accs[nt][2] = accs[nt][2] * scale + b1.x;
        accs[nt][3] = accs[nt][3] * scale + b1.y;
    }

    float m0 = -1e30f, m1 = -1e30f;
#pragma unroll
    for (int nt = 0; nt < 8; nt++) {
        m0 = fmaxf(m0, fmaxf(accs[nt][0], accs[nt][1]));
        m1 = fmaxf(m1, fmaxf(accs[nt][2], accs[nt][3]));
    }
    m0 = fmaxf(m0, __shfl_xor_sync(0xffffffffu, m0, 1));
    m0 = fmaxf(m0, __shfl_xor_sync(0xffffffffu, m0, 2));
    m1 = fmaxf(m1, __shfl_xor_sync(0xffffffffu, m1, 1));
    m1 = fmaxf(m1, __shfl_xor_sync(0xffffffffu, m1, 2));

    float s0 = 0.f, s1 = 0.f;
#pragma unroll
    for (int nt = 0; nt < 8; nt++) {
        accs[nt][0] = expf(accs[nt][0] - m0);
        accs[nt][1] = expf(accs[nt][1] - m0);
        accs[nt][2] = expf(accs[nt][2] - m1);
        accs[nt][3] = expf(accs[nt][3] - m1);
        s0 += accs[nt][0] + accs[nt][1];
        s1 += accs[nt][2] + accs[nt][3];
    }
    s0 += __shfl_xor_sync(0xffffffffu, s0, 1);
    s0 += __shfl_xor_sync(0xffffffffu, s0, 2);
    s1 += __shfl_xor_sync(0xffffffffu, s1, 1);
    s1 += __shfl_xor_sync(0xffffffffu, s1, 2);
    float inv0 = 1.0f / s0, inv1 = 1.0f / s1;

    float acco[4][4];
#pragma unroll
    for (int i = 0; i < 4; i++)
#pragma unroll
        for (int j = 0; j < 4; j++) acco[i][j] = 0.f;

#pragma unroll
    for (int kk = 0; kk < 4; kk++) {
        uint32_t pa[4];
        pa[0] = packbf(accs[2 * kk][0] * inv0, accs[2 * kk][1] * inv0);
        pa[1] = packbf(accs[2 * kk][2] * inv1, accs[2 * kk][3] * inv1);
        pa[2] = packbf(accs[2 * kk + 1][0] * inv0, accs[2 * kk + 1][1] * inv0);
        pa[3] = packbf(accs[2 * kk + 1][2] * inv1, accs[2 * kk + 1][3] * inv1);
#pragma unroll
        for (int np = 0; np < 2; np++) {
            uint32_t vb[4];
            ldsm_x4_t(vb, &Vs[kk * 16 + (lane & 15)][np * 16 + (lane >> 4) * 8]);
            mma_bf16(acco[np * 2],     pa, vb[0], vb[1]);
            mma_bf16(acco[np * 2 + 1], pa, vb[2], vb[3]);
        }
    }

    int t0 = sidx[ri], t1 = sidx[ri + 8];
#pragma unroll
    for (int nt = 0; nt < 4; nt++) {
        int ch = head * HD + nt * 8 + (lane & 3) * 2;
        *(uint32_t*)(out + (size_t)t0 * C + ch) = packbf(acco[nt][0], acco[nt][1]);
        *(uint32_t*)(out + (size_t)t1 * C + ch) = packbf(acco[nt][2], acco[nt][3]);
    }
}

// ---------------------------------------------------------------------------
// Launch
// ---------------------------------------------------------------------------
extern "C" void kernel_launch(void* const* d_in, const int* in_sizes, int n_in,
                              void* d_out, int out_size)
{
    const float* x       = (const float*)d_in[0];
    const float* norm1_g = (const float*)d_in[1];
    const float* norm1_b = (const float*)d_in[2];
    const float* qkv_w   = (const float*)d_in[3];
    const float* qkv_b   = (const float*)d_in[4];
    const float* rpb     = (const float*)d_in[5];
    const float* proj_w  = (const float*)d_in[6];
    const float* proj_b  = (const float*)d_in[7];
    const float* norm2_g = (const float*)d_in[8];
    const float* norm2_b = (const float*)d_in[9];
    const float* fc1_w   = (const float*)d_in[10];
    const float* fc1_b   = (const float*)d_in[11];
    const float* fc2_w   = (const float*)d_in[12];
    const float* fc2_b   = (const float*)d_in[13];
    float* out = (float*)d_out;

    __nv_bfloat16 *hb, *qkvb, *attnb, *gb, *wqkv, *wproj, *wfc1, *wfc2;
    float *x2, *bm;
    cudaGetSymbolAddress((void**)&hb,    s_hb);
    cudaGetSymbolAddress((void**)&qkvb,  s_qkvb);
    cudaGetSymbolAddress((void**)&attnb, s_attnb);
    cudaGetSymbolAddress((void**)&x2,    s_x2);
    cudaGetSymbolAddress((void**)&gb,    s_gb);
    cudaGetSymbolAddress((void**)&bm,    s_bm);
    cudaGetSymbolAddress((void**)&wqkv,  s_wqkv);
    cudaGetSymbolAddress((void**)&wproj, s_wproj);
    cudaGetSymbolAddress((void**)&wfc1,  s_wfc1);
    cudaGetSymbolAddress((void**)&wfc2,  s_wfc2);

    cudaFuncSetAttribute(gemm_bf16_kernel<0, 0, 1>,
                         cudaFuncAttributeMaxDynamicSharedMemorySize, GT_SMEM);
    cudaFuncSetAttribute(gemm_bf16_kernel<0, 1, 0>,
                         cudaFuncAttributeMaxDynamicSharedMemorySize, GT_SMEM);
    cudaFuncSetAttribute(gemm_bf16_kernel<1, 0, 1>,
                         cudaFuncAttributeMaxDynamicSharedMemorySize, GT_SMEM);

    // 0) weight conversions + bias/mask table
    f2bf_kernel<<<(C * C3 + 255) / 256, 256>>>(qkv_w, wqkv, C * C3);
    f2bf_kernel<<<(C * C + 255) / 256, 256>>>(proj_w, wproj, C * C);
    f2bf_kernel<<<(C * HID + 255) / 256, 256>>>(fc1_w, wfc1, C * HID);
    f2bf_kernel<<<(HID * C + 255) / 256, 256>>>(fc2_w, wfc2, HID * C);
    {
        dim3 grid(8, NHEAD);
        biasmask_kernel<<<grid, 256>>>(rpb, bm);
    }

    // 1) LN1 -> bf16
    ln_kernel<<<TOK / 8, 256>>>(x, norm1_g, norm1_b, hb);

    // 2) QKV GEMM -> bf16
    gemm_bf16_kernel<0, 0, 1><<<dim3(C3 / 128, TOK / 256), 256, GT_SMEM>>>(
        hb, wqkv, qkv_b, nullptr, nullptr, qkvb, TOK, C3, C);

    // 3) Attention -> bf16
    attn_mma_kernel<<<dim3(NWIN, NHEAD), 128>>>(qkvb, bm, attnb);

    // 4) proj + residual (x) -> fp32 x2
    gemm_bf16_kernel<0, 1, 0><<<dim3(C / 128, TOK / 256), 256, GT_SMEM>>>(
        attnb, wproj, proj_b, x, x2, nullptr, TOK, C, C);

    // 5) LN2 -> bf16
    ln_kernel<<<TOK / 8, 256>>>(x2, norm2_g, norm2_b, hb);

    // 6) fc1 + gelu -> bf16
    gemm_bf16_kernel<1, 0, 1><<<dim3(HID / 128, TOK / 256), 256, GT_SMEM>>>(
        hb, wfc1, fc1_b, nullptr, nullptr, gb, TOK, HID, C);

    // 7) fc2 + residual (x2) -> fp32 out
    gemm_bf16_kernel<0, 1, 0><<<dim3(C / 128, TOK / 256), 256, GT_SMEM>>>(
        gb, wfc2, fc2_b, x2, out, nullptr, TOK, C, HID);
}

// round 14
// speedup vs baseline: 1.0882x; 1.0882x over previous
#include <cuda_runtime.h>
#include <cuda_bf16.h>
#include <math.h>
#include <stdint.h>

// Problem constants
#define TOK   100352          // 2*16*56*56
#define C     384
#define C3    1152
#define HID   1536
#define NHEAD 12
#define HD    32
#define NWIN  1568            // 2 * 4*14*14

// ---------------------------------------------------------------------------
// Scratch (device globals; allocation-free)
// ---------------------------------------------------------------------------
__device__ __nv_bfloat16 s_hb   [(size_t)TOK * C];
__device__ __nv_bfloat16 s_qkvb [(size_t)TOK * C3];
__device__ __nv_bfloat16 s_attnb[(size_t)TOK * C];
__device__ float         s_x2   [(size_t)TOK * C];
__device__ __nv_bfloat16 s_gb   [(size_t)TOK * HID];
__device__ float         s_bm   [8 * NHEAD * 64 * 64];
// bf16 weight copies ([K][N] row-major)
__device__ __nv_bfloat16 s_wqkv [(size_t)C * C3];
__device__ __nv_bfloat16 s_wproj[(size_t)C * C];
__device__ __nv_bfloat16 s_wfc1 [(size_t)C * HID];
__device__ __nv_bfloat16 s_wfc2 [(size_t)HID * C];

// ---------------------------------------------------------------------------
// fp32 -> bf16 conversion (weights, once per launch)
// ---------------------------------------------------------------------------
__global__ void f2bf_kernel(const float* __restrict__ in,
                            __nv_bfloat16* __restrict__ out, int n)
{
    int i = blockIdx.x * 256 + threadIdx.x;
    if (i < n) out[i] = __float2bfloat16(in[i]);
}

// ---------------------------------------------------------------------------
// Bias+mask table: [wtype 0..7][head][i][j]
// ---------------------------------------------------------------------------
__global__ void biasmask_kernel(const float* __restrict__ rpb,
                                float* __restrict__ bm)
{
    int wtype = blockIdx.x, head = blockIdx.y;
    int bd = (wtype >> 2) & 1, bh = (wtype >> 1) & 1, bw = wtype & 1;
    float* dst = bm + ((size_t)(wtype * NHEAD + head)) * 4096;
    for (int e = threadIdx.x; e < 4096; e += 256) {
        int i = e >> 6, j = e & 63;
        int odi = i >> 4, ohi = (i >> 2) & 3, owi = i & 3;
        int odj = j >> 4, ohj = (j >> 2) & 3, owj = j & 3;
        int li = (bd ? 1 + (odi >> 1) : 0) * 9 + (bh ? 1 + (ohi >> 1) : 0) * 3
               + (bw ? 1 + (owi >> 1) : 0);
        int lj = (bd ? 1 + (odj >> 1) : 0) * 9 + (bh ? 1 + (ohj >> 1) : 0) * 3
               + (bw ? 1 + (owj >> 1) : 0);
        float v = rpb[((odi - odj + 3) * 49 + (ohi - ohj + 3) * 7 +
                       (owi - owj + 3)) * NHEAD + head];
        if (li != lj) v -= 100.0f;
        dst[e] = v;
    }
}

// ---------------------------------------------------------------------------
// LayerNorm: one warp per token, C=384, bf16 output
// ---------------------------------------------------------------------------
__global__ void ln_kernel(const float* __restrict__ x,
                          const float* __restrict__ g,
                          const float* __restrict__ b,
                          __nv_bfloat16* __restrict__ y)
{
    int token = blockIdx.x * 8 + (threadIdx.x >> 5);
    int lane  = threadIdx.x & 31;
    const float* xr = x + (size_t)token * C;
    float v[12];
    float s = 0.f;
#pragma unroll
    for (int i = 0; i < 12; i++) { v[i] = xr[lane + i * 32]; s += v[i]; }
#pragma unroll
    for (int o = 16; o; o >>= 1) s += __shfl_xor_sync(0xffffffffu, s, o);
    float mu = s * (1.0f / 384.0f);
    float q = 0.f;
#pragma unroll
    for (int i = 0; i < 12; i++) { float d = v[i] - mu; q += d * d; }
#pragma unroll
    for (int o = 16; o; o >>= 1) q += __shfl_xor_sync(0xffffffffu, q, o);
    float rstd = rsqrtf(q * (1.0f / 384.0f) + 1e-5f);
    __nv_bfloat16* yr = y + (size_t)token * C;
#pragma unroll
    for (int i = 0; i < 12; i++) {
        int c = lane + i * 32;
        yr[c] = __float2bfloat16((v[i] - mu) * rstd * g[c] + b[c]);
    }
}

// ---------------------------------------------------------------------------
// MMA helpers
// ---------------------------------------------------------------------------
__device__ __forceinline__ float gelu_exact(float x)
{
    return 0.5f * x * (1.0f + erff(x * 0.70710678118654752f));
}

__device__ __forceinline__ void cp_async16(void* smem, const void* gmem)
{
    uint32_t s = (uint32_t)__cvta_generic_to_shared(smem);
    asm volatile("cp.async.cg.shared.global [%0], [%1], 16;\n" :: "r"(s), "l"(gmem));
}
__device__ __forceinline__ void cp_commit()
{
    asm volatile("cp.async.commit_group;\n");
}
template <int N>
__device__ __forceinline__ void cp_wait()
{
    asm volatile("cp.async.wait_group %0;\n" :: "n"(N));
}

__device__ __forceinline__ void ldsm_x4(uint32_t* r, const void* p)
{
    uint32_t a = (uint32_t)__cvta_generic_to_shared(p);
    asm volatile("ldmatrix.sync.aligned.m8n8.x4.shared.b16 {%0,%1,%2,%3}, [%4];"
                 : "=r"(r[0]), "=r"(r[1]), "=r"(r[2]), "=r"(r[3]) : "r"(a));
}
__device__ __forceinline__ void ldsm_x4_t(uint32_t* r, const void* p)
{
    uint32_t a = (uint32_t)__cvta_generic_to_shared(p);
    asm volatile("ldmatrix.sync.aligned.m8n8.x4.trans.shared.b16 {%0,%1,%2,%3}, [%4];"
                 : "=r"(r[0]), "=r"(r[1]), "=r"(r[2]), "=r"(r[3]) : "r"(a));
}

__device__ __forceinline__ void mma_bf16(float* d, const uint32_t* a,
                                         uint32_t b0, uint32_t b1)
{
    asm volatile(
        "mma.sync.aligned.m16n8k16.row.col.f32.bf16.bf16.f32 "
        "{%0,%1,%2,%3}, {%4,%5,%6,%7}, {%8,%9}, {%0,%1,%2,%3};\n"
        : "+f"(d[0]), "+f"(d[1]), "+f"(d[2]), "+f"(d[3])
        : "r"(a[0]), "r"(a[1]), "r"(a[2]), "r"(a[3]), "r"(b0), "r"(b1));
}

__device__ __forceinline__ uint32_t packbf(float a, float b)
{
    __nv_bfloat162 t = __floats2bfloat162_rn(a, b);
    return *(uint32_t*)&t;
}

// ---------------------------------------------------------------------------
// bf16 tensor-core GEMM: 128x128 CTA tile, 128 threads = 4 warps (2M x 2N),
// warp tile 64x64. BK=64, 2-stage cp.async ring, 3 CTAs/SM (12 warps).
// Per warp per k16 step: 8 ldmatrix feed 32 mma (4:1 density).
// A bf16 [M][K], B bf16 [K][N]. fp32 accumulate.
// ---------------------------------------------------------------------------
#define GSTAGES 2
#define A_STG   (128 * 72)        // bf16 elems per A stage (72 = 64 + 8 pad)
#define B_STG   (64 * 136)        // bf16 elems per B stage (136 = 128 + 8 pad)
#define GT_SMEM ((GSTAGES * (A_STG + B_STG)) * 2)   // 71.7 KB -> 3 CTAs/SM

// OUTBF: 0 -> write fp32 Cout; 1 -> write bf16 Coutb
template <int ACT, int RES, int OUTBF>
__global__ __launch_bounds__(128, 3)
void gemm_bf16_kernel(const __nv_bfloat16* __restrict__ A,
                      const __nv_bfloat16* __restrict__ B,
                      const float* __restrict__ bias,
                      const float* __restrict__ res,
                      float* __restrict__ Cout,
                      __nv_bfloat16* __restrict__ Coutb,
                      int M, int N, int K)
{
    extern __shared__ __nv_bfloat16 sm[];
    __nv_bfloat16* As = sm;                     // [GSTAGES][128][72]
    __nv_bfloat16* Bs = sm + GSTAGES * A_STG;   // [GSTAGES][64][136]

    int tid  = threadIdx.x;
    int lane = tid & 31;
    int wid  = tid >> 5;
    int wm   = wid & 1;        // warp row 0..1 (64 rows each)
    int wn   = wid >> 1;       // warp col 0..1 (64 cols each)
    int bm   = blockIdx.y * 128;
    int bn   = blockIdx.x * 128;

    float acc[4][8][4];
#pragma unroll
    for (int i = 0; i < 4; i++)
#pragma unroll
        for (int j = 0; j < 8; j++)
#pragma unroll
            for (int l = 0; l < 4; l++) acc[i][j][l] = 0.f;

    const int CH = K >> 6;      // 64-wide K chunks

    auto fill = [&](int c) {
        int s = c & 1;
        __nv_bfloat16* aS = As + s * A_STG;
        __nv_bfloat16* bS = Bs + s * B_STG;
        const __nv_bfloat16* ag = A + (size_t)bm * K + c * 64;
        const __nv_bfloat16* bg = B + (size_t)(c * 64) * N + bn;
#pragma unroll
        for (int i = 0; i < 8; i++) {           // A: 128 rows x 8 chunks of 8
            int idx = tid + i * 128;
            int row = idx >> 3, c8 = idx & 7;
            cp_async16(aS + row * 72 + c8 * 8,
                       ag + (size_t)row * K + c8 * 8);
        }
#pragma unroll
        for (int i = 0; i < 8; i++) {           // B: 64 rows x 16 chunks of 8
            int idx = tid + i * 128;
            int row = idx >> 4, c16 = idx & 15;
            cp_async16(bS + row * 136 + c16 * 8,
                       bg + (size_t)row * N + c16 * 8);
        }
        cp_commit();
    };

    fill(0);
    fill(1);

    // precomputed lane fragment offsets
    int a_ro = (lane & 15);            // A frag row within 16
    int a_co = (lane >> 4) * 8;        // A frag k sub-col
    int b_ro = (lane & 15);            // B frag k row within 16
    int b_co = (lane >> 4) * 8;        // B frag n sub-col

    for (int kt = 0; kt < CH; kt++) {
        cp_wait<1>();
        __syncthreads();

        int cur = kt & 1;
        const __nv_bfloat16* aS = As + cur * A_STG;
        const __nv_bfloat16* bS = Bs + cur * B_STG;

#pragma unroll
        for (int ks = 0; ks < 4; ks++) {
            uint32_t af[4][4];
            uint32_t bf[4][4];
#pragma unroll
            for (int mt = 0; mt < 4; mt++)
                ldsm_x4(af[mt], aS + (wm * 64 + mt * 16 + a_ro) * 72
                                   + ks * 16 + a_co);
#pragma unroll
            for (int np = 0; np < 4; np++)
                ldsm_x4_t(bf[np], bS + (ks * 16 + b_ro) * 136
                                     + wn * 64 + np * 16 + b_co);
#pragma unroll
            for (int mt = 0; mt < 4; mt++)
#pragma unroll
                for (int np = 0; np < 4; np++) {
                    mma_bf16(acc[mt][np * 2],     af[mt], bf[np][0], bf[np][1]);
                    mma_bf16(acc[mt][np * 2 + 1], af[mt], bf[np][2], bf[np][3]);
                }
        }

        __syncthreads();                       // stage reusable
        if (kt + 2 < CH) fill(kt + 2);
    }

    // epilogue
#pragma unroll
    for (int mt = 0; mt < 4; mt++) {
        int row = bm + wm * 64 + mt * 16 + (lane >> 2);
#pragma unroll
        for (int nt = 0; nt < 8; nt++) {
            int col = bn + wn * 64 + nt * 8 + (lane & 3) * 2;
            float bv0 = bias[col], bv1 = bias[col + 1];

            float v0 = acc[mt][nt][0] + bv0;
            float v1 = acc[mt][nt][1] + bv1;
            float v2 = acc[mt][nt][2] + bv0;
            float v3 = acc[mt][nt][3] + bv1;
            if (ACT) {
                v0 = gelu_exact(v0); v1 = gelu_exact(v1);
                v2 = gelu_exact(v2); v3 = gelu_exact(v3);
            }
            if (RES) {
                float2 q0 = *(const float2*)(res + (size_t)row * N + col);
                float2 q1 = *(const float2*)(res + (size_t)(row + 8) * N + col);
                v0 += q0.x; v1 += q0.y; v2 += q1.x; v3 += q1.y;
            }
            if (OUTBF) {
                *(uint32_t*)(Coutb + (size_t)row * N + col)       = packbf(v0, v1);
                *(uint32_t*)(Coutb + (size_t)(row + 8) * N + col) = packbf(v2, v3);
            } else {
                *(float2*)(Cout + (size_t)row * N + col)       = make_float2(v0, v1);
                *(float2*)(Cout + (size_t)(row + 8) * N + col) = make_float2(v2, v3);
            }
        }
    }
}

// ---------------------------------------------------------------------------
// Tensor-core attention: one block per (window, head), 128 threads (4 warps).
// ---------------------------------------------------------------------------
__global__ __launch_bounds__(128)
void attn_mma_kernel(const __nv_bfloat16* __restrict__ qkv,
                     const float* __restrict__ bm,
                     __nv_bfloat16* __restrict__ out)
{
    __shared__ __nv_bfloat16 Qs[64][40];
    __shared__ __nv_bfloat16 Ks[64][40];
    __shared__ __nv_bfloat16 Vs[64][40];
    __shared__ int sidx[64];

    int wi = blockIdx.x, head = blockIdx.y;
    int tid = threadIdx.x;
    int lane = tid & 31, w = tid >> 5;

    int b  = wi / 784;
    int rem = wi % 784;
    int wd = rem / 196;
    int r2 = rem % 196;
    int wh = r2 / 14;
    int ww = r2 % 14;
    int wtype = ((wd == 3) ? 4 : 0) | ((wh == 13) ? 2 : 0) | ((ww == 13) ? 1 : 0);

    if (tid < 64) {
        int od = tid >> 4, oh = (tid >> 2) & 3, ow = tid & 3;
        int d = wd * 4 + od, h = wh * 4 + oh, wq = ww * 4 + ow;
        int sd = (d + 2) & 15;
        int sh = h + 2; if (sh >= 56) sh -= 56;
        int sw = wq + 2; if (sw >= 56) sw -= 56;
        sidx[tid] = ((b * 16 + sd) * 56 + sh) * 56 + sw;
    }
    __syncthreads();

    for (int e = tid; e < 768; e += 128) {
        int tens = e >> 8;
        int r = e & 255;
        int n = r >> 2, c = r & 3;
        const uint4* src = (const uint4*)(qkv + (size_t)sidx[n] * C3 +
                                          tens * C + head * HD) + c;
        uint4 v = *src;
        __nv_bfloat16* dst = (tens == 0) ? &Qs[n][c * 8]
                           : (tens == 1) ? &Ks[n][c * 8] : &Vs[n][c * 8];
        *(uint4*)dst = v;
    }
    __syncthreads();

    float accs[8][4];
#pragma unroll
    for (int i = 0; i < 8; i++)
#pragma unroll
        for (int j = 0; j < 4; j++) accs[i][j] = 0.f;

#pragma unroll
    for (int ks = 0; ks < 2; ks++) {
        uint32_t qa[4];
        ldsm_x4(qa, &Qs[w * 16 + (lane & 15)][ks * 16 + (lane >> 4) * 8]);
#pragma unroll
        for (int nt = 0; nt < 4; nt++) {
            uint32_t kb[4];
            ldsm_x4(kb, &Ks[nt * 16 + ((lane >> 4) & 1) * 8 + (lane & 7)]
                        [ks * 16 + ((lane >> 3) & 1) * 8]);
            mma_bf16(accs[nt * 2],     qa, kb[0], kb[1]);
            mma_bf16(accs[nt * 2 + 1], qa, kb[2], kb[3]);
        }
    }

    const float scale = 0.17677669529663687f;
    int ri = w * 16 + (lane >> 2);
    const float* bmp = bm + ((size_t)(wtype * NHEAD + head)) * 4096;
#pragma unroll
    for (int nt = 0; nt < 8; nt++) {
        int j = nt * 8 + (lane & 3) * 2;
        float2 b0 = *(const float2*)(bmp + ri * 64 + j);
        float2 b1 = *(const float2*)(bmp + (ri + 8) * 64 + j);
        accs[nt][0] = accs[nt][0] * scale + b0.x;
        accs[nt][1] = accs[nt][1] * scale + b0.y;
        accs[nt][2] = accs[nt][2] * scale + b1.x;
        accs[nt][3] = accs[nt][3] * scale + b1.y;
    }

    float m0 = -1e30f, m1 = -1e30f;
#pragma unroll
    for (int nt = 0; nt < 8; nt++) {
        m0 = fmaxf(m0, fmaxf(accs[nt][0], accs[nt][1]));
        m1 = fmaxf(m1, fmaxf(accs[nt][2], accs[nt][3]));
    }
    m0 = fmaxf(m0, __shfl_xor_sync(0xffffffffu, m0, 1));
    m0 = fmaxf(m0, __shfl_xor_sync(0xffffffffu, m0, 2));
    m1 = fmaxf(m1, __shfl_xor_sync(0xffffffffu, m1, 1));
    m1 = fmaxf(m1, __shfl_xor_sync(0xffffffffu, m1, 2));

    float s0 = 0.f, s1 = 0.f;
#pragma unroll
    for (int nt = 0; nt < 8; nt++) {
        accs[nt][0] = expf(accs[nt][0] - m0);
        accs[nt][1] = expf(accs[nt][1] - m0);
        accs[nt][2] = expf(accs[nt][2] - m1);
        accs[nt][3] = expf(accs[nt][3] - m1);
        s0 += accs[nt][0] + accs[nt][1];
        s1 += accs[nt][2] + accs[nt][3];
    }
    s0 += __shfl_xor_sync(0xffffffffu, s0, 1);
    s0 += __shfl_xor_sync(0xffffffffu, s0, 2);
    s1 += __shfl_xor_sync(0xffffffffu, s1, 1);
    s1 += __shfl_xor_sync(0xffffffffu, s1, 2);
    float inv0 = 1.0f / s0, inv1 = 1.0f / s1;

    float acco[4][4];
#pragma unroll
    for (int i = 0; i < 4; i++)
#pragma unroll
        for (int j = 0; j < 4; j++) acco[i][j] = 0.f;

#pragma unroll
    for (int kk = 0; kk < 4; kk++) {
        uint32_t pa[4];
        pa[0] = packbf(accs[2 * kk][0] * inv0, accs[2 * kk][1] * inv0);
        pa[1] = packbf(accs[2 * kk][2] * inv1, accs[2 * kk][3] * inv1);
        pa[2] = packbf(accs[2 * kk + 1][0] * inv0, accs[2 * kk + 1][1] * inv0);
        pa[3] = packbf(accs[2 * kk + 1][2] * inv1, accs[2 * kk + 1][3] * inv1);
#pragma unroll
        for (int np = 0; np < 2; np++) {
            uint32_t vb[4];
            ldsm_x4_t(vb, &Vs[kk * 16 + (lane & 15)][np * 16 + (lane >> 4) * 8]);
            mma_bf16(acco[np * 2],     pa, vb[0], vb[1]);
            mma_bf16(acco[np * 2 + 1], pa, vb[2], vb[3]);
        }
    }

    int t0 = sidx[ri], t1 = sidx[ri + 8];
#pragma unroll
    for (int nt = 0; nt < 4; nt++) {
        int ch = head * HD + nt * 8 + (lane & 3) * 2;
        *(uint32_t*)(out + (size_t)t0 * C + ch) = packbf(acco[nt][0], acco[nt][1]);
        *(uint32_t*)(out + (size_t)t1 * C + ch) = packbf(acco[nt][2], acco[nt][3]);
    }
}

// ---------------------------------------------------------------------------
// Launch
// ---------------------------------------------------------------------------
extern "C" void kernel_launch(void* const* d_in, const int* in_sizes, int n_in,
                              void* d_out, int out_size)
{
    const float* x       = (const float*)d_in[0];
    const float* norm1_g = (const float*)d_in[1];
    const float* norm1_b = (const float*)d_in[2];
    const float* qkv_w   = (const float*)d_in[3];
    const float* qkv_b   = (const float*)d_in[4];
    const float* rpb     = (const float*)d_in[5];
    const float* proj_w  = (const float*)d_in[6];
    const float* proj_b  = (const float*)d_in[7];
    const float* norm2_g = (const float*)d_in[8];
    const float* norm2_b = (const float*)d_in[9];
    const float* fc1_w   = (const float*)d_in[10];
    const float* fc1_b   = (const float*)d_in[11];
    const float* fc2_w   = (const float*)d_in[12];
    const float* fc2_b   = (const float*)d_in[13];
    float* out = (float*)d_out;

    __nv_bfloat16 *hb, *qkvb, *attnb, *gb, *wqkv, *wproj, *wfc1, *wfc2;
    float *x2, *bm;
    cudaGetSymbolAddress((void**)&hb,    s_hb);
    cudaGetSymbolAddress((void**)&qkvb,  s_qkvb);
    cudaGetSymbolAddress((void**)&attnb, s_attnb);
    cudaGetSymbolAddress((void**)&x2,    s_x2);
    cudaGetSymbolAddress((void**)&gb,    s_gb);
    cudaGetSymbolAddress((void**)&bm,    s_bm);
    cudaGetSymbolAddress((void**)&wqkv,  s_wqkv);
    cudaGetSymbolAddress((void**)&wproj, s_wproj);
    cudaGetSymbolAddress((void**)&wfc1,  s_wfc1);
    cudaGetSymbolAddress((void**)&wfc2,  s_wfc2);

    cudaFuncSetAttribute(gemm_bf16_kernel<0, 0, 1>,
                         cudaFuncAttributeMaxDynamicSharedMemorySize, GT_SMEM);
    cudaFuncSetAttribute(gemm_bf16_kernel<0, 1, 0>,
                         cudaFuncAttributeMaxDynamicSharedMemorySize, GT_SMEM);
    cudaFuncSetAttribute(gemm_bf16_kernel<1, 0, 1>,
                         cudaFuncAttributeMaxDynamicSharedMemorySize, GT_SMEM);

    // 0) weight conversions + bias/mask table
    f2bf_kernel<<<(C * C3 + 255) / 256, 256>>>(qkv_w, wqkv, C * C3);
    f2bf_kernel<<<(C * C + 255) / 256, 256>>>(proj_w, wproj, C * C);
    f2bf_kernel<<<(C * HID + 255) / 256, 256>>>(fc1_w, wfc1, C * HID);
    f2bf_kernel<<<(HID * C + 255) / 256, 256>>>(fc2_w, wfc2, HID * C);
    {
        dim3 grid(8, NHEAD);
        biasmask_kernel<<<grid, 256>>>(rpb, bm);
    }

    // 1) LN1 -> bf16
    ln_kernel<<<TOK / 8, 256>>>(x, norm1_g, norm1_b, hb);

    // 2) QKV GEMM -> bf16
    gemm_bf16_kernel<0, 0, 1><<<dim3(C3 / 128, TOK / 128), 128, GT_SMEM>>>(
        hb, wqkv, qkv_b, nullptr, nullptr, qkvb, TOK, C3, C);

    // 3) Attention -> bf16
    attn_mma_kernel<<<dim3(NWIN, NHEAD), 128>>>(qkvb, bm, attnb);

    // 4) proj + residual (x) -> fp32 x2
    gemm_bf16_kernel<0, 1, 0><<<dim3(C / 128, TOK / 128), 128, GT_SMEM>>>(
        attnb, wproj, proj_b, x, x2, nullptr, TOK, C, C);

    // 5) LN2 -> bf16
    ln_kernel<<<TOK / 8, 256>>>(x2, norm2_g, norm2_b, hb);

    // 6) fc1 + gelu -> bf16
    gemm_bf16_kernel<1, 0, 1><<<dim3(HID / 128, TOK / 128), 128, GT_SMEM>>>(
        hb, wfc1, fc1_b, nullptr, nullptr, gb, TOK, HID, C);

    // 7) fc2 + residual (x2) -> fp32 out
    gemm_bf16_kernel<0, 1, 0><<<dim3(C / 128, TOK / 128), 128, GT_SMEM>>>(
        gb, wfc2, fc2_b, x2, out, nullptr, TOK, C, HID);
}